// round 16
// baseline (speedup 1.0000x reference)
#include <cuda_runtime.h>
#include <cuda_bf16.h>
#include <cstdint>
#include <math.h>

#define NTOK 8192
#define CDIM 1024
#define HDIM 2048
#define NEXP 8

#define BM 128
#define BN 128
#define BK 64            // bf16 elements per k-tile (128 bytes per row)
#define STAGES 3

// ---------------- device scratch (no allocations allowed) ----------------
__device__ __nv_bfloat16 g_xb[(size_t)NTOK * CDIM];            // x bf16
__device__ __nv_bfloat16 g_h [(size_t)NTOK * HDIM];            // hidden bf16
__device__ __nv_bfloat16 g_w1t[(size_t)NEXP * HDIM * CDIM];    // (W1-0.5)^T [e][n][k]
__device__ __nv_bfloat16 g_w2t[(size_t)NEXP * CDIM * HDIM];    // W2^T      [e][n][k]
__device__ int   g_tok[NEXP * NTOK];
__device__ int   g_cnt[NEXP];
__device__ float g_score[NTOK];
__device__ float g_xsum[NTOK];

// ---------------- helpers ----------------
__device__ __forceinline__ uint32_t smem_u32(const void* p) {
    return static_cast<uint32_t>(__cvta_generic_to_shared(p));
}
__device__ __forceinline__ void ldsm_x4(uint32_t r[4], uint32_t addr) {
    asm volatile("ldmatrix.sync.aligned.m8n8.x4.shared.b16 {%0,%1,%2,%3}, [%4];"
                 : "=r"(r[0]), "=r"(r[1]), "=r"(r[2]), "=r"(r[3]) : "r"(addr));
}
__device__ __forceinline__ void mma_bf16(float c[4], const uint32_t a[4],
                                         uint32_t b0, uint32_t b1) {
    asm volatile(
        "mma.sync.aligned.m16n8k16.row.col.f32.bf16.bf16.f32 "
        "{%0,%1,%2,%3}, {%4,%5,%6,%7}, {%8,%9}, {%0,%1,%2,%3};\n"
        : "+f"(c[0]), "+f"(c[1]), "+f"(c[2]), "+f"(c[3])
        : "r"(a[0]), "r"(a[1]), "r"(a[2]), "r"(a[3]), "r"(b0), "r"(b1));
}
__device__ __forceinline__ void cpa16(uint32_t dst, const void* src) {
    asm volatile("cp.async.cg.shared.global [%0], [%1], 16;" :: "r"(dst), "l"(src) : "memory");
}
__device__ __forceinline__ void cpa_commit() {
    asm volatile("cp.async.commit_group;" ::: "memory");
}
__device__ __forceinline__ void cpa_wait1() {
    asm volatile("cp.async.wait_group 1;" ::: "memory");
}
__device__ __forceinline__ float gelu_exact(float v) {
    return 0.5f * v * (1.0f + erff(v * 0.70710678118654752f));
}

// ---------------- kernel 0: zero bucket counters ----------------
__global__ void zero_cnt_kernel() {
    if (threadIdx.x < NEXP) g_cnt[threadIdx.x] = 0;
}

// ---------------- kernel 1: routing — 2 tokens/warp (bit-identical math) --
__global__ __launch_bounds__(256) void route_kernel(
    const float* __restrict__ x, const float* __restrict__ Wr,
    const float* __restrict__ wg)
{
    __shared__ float wgn_s[NEXP][16];
    const int tid = threadIdx.x;
    if (tid < NEXP) {
        float row[16];
        float nrm = 0.f;
        #pragma unroll
        for (int j = 0; j < 16; ++j) { row[j] = wg[tid * 16 + j]; nrm += row[j] * row[j]; }
        nrm = fmaxf(sqrtf(nrm), 1e-4f);
        #pragma unroll
        for (int j = 0; j < 16; ++j) wgn_s[tid][j] = row[j] / nrm;
    }
    __syncthreads();

    const int lane = tid & 31;
    const int gw   = (blockIdx.x * blockDim.x + tid) >> 5;
    const int t0   = gw * 2;                       // 2 tokens per warp

    float acc[2][16];
    float sx[2] = {0.f, 0.f};
    #pragma unroll
    for (int ti = 0; ti < 2; ++ti)
        #pragma unroll
        for (int j = 0; j < 16; ++j) acc[ti][j] = 0.f;

    for (int c = 0; c < 32; c += 2) {
        const int kA = c * 32 + lane;
        const int kB = kA + 32;
        float wrA[16], wrB[16];
        #pragma unroll
        for (int j = 0; j < 16; ++j) wrA[j] = Wr[j * CDIM + kA];
        #pragma unroll
        for (int j = 0; j < 16; ++j) wrB[j] = Wr[j * CDIM + kB];
        float xvA[2], xvB[2];
        #pragma unroll
        for (int ti = 0; ti < 2; ++ti) {
            xvA[ti] = x[(size_t)(t0 + ti) * CDIM + kA];
            xvB[ti] = x[(size_t)(t0 + ti) * CDIM + kB];
        }
        #pragma unroll
        for (int ti = 0; ti < 2; ++ti) {
            g_xb[(size_t)(t0 + ti) * CDIM + kA] = __float2bfloat16(xvA[ti]);
            g_xb[(size_t)(t0 + ti) * CDIM + kB] = __float2bfloat16(xvB[ti]);
        }
        #pragma unroll
        for (int ti = 0; ti < 2; ++ti) {
            sx[ti] += xvA[ti];
            #pragma unroll
            for (int j = 0; j < 16; ++j) acc[ti][j] = fmaf(xvA[ti], wrA[j], acc[ti][j]);
        }
        #pragma unroll
        for (int ti = 0; ti < 2; ++ti) {
            sx[ti] += xvB[ti];
            #pragma unroll
            for (int j = 0; j < 16; ++j) acc[ti][j] = fmaf(xvB[ti], wrB[j], acc[ti][j]);
        }
    }
    #pragma unroll
    for (int ti = 0; ti < 2; ++ti) {
        #pragma unroll
        for (int j = 0; j < 16; ++j)
            #pragma unroll
            for (int off = 16; off > 0; off >>= 1)
                acc[ti][j] += __shfl_xor_sync(0xffffffffu, acc[ti][j], off);
        #pragma unroll
        for (int off = 16; off > 0; off >>= 1)
            sx[ti] += __shfl_xor_sync(0xffffffffu, sx[ti], off);
    }

    if (lane < 2) {
        const int t = t0 + lane;
        float logit[NEXP];
        float best = -1e30f; int be = 0;
        #pragma unroll
        for (int e = 0; e < NEXP; ++e) {
            float l = 0.f;
            #pragma unroll
            for (int j = 0; j < 16; ++j) l += acc[lane][j] * wgn_s[e][j];
            logit[e] = l;
            if (l > best) { best = l; be = e; }
        }
        float denom = 0.f;
        #pragma unroll
        for (int e = 0; e < NEXP; ++e) denom += expf(logit[e] - best);
        g_score[t] = 1.0f / denom;
        g_xsum[t]  = sx[lane];
        int pos = atomicAdd(&g_cnt[be], 1);
        g_tok[be * NTOK + pos] = t;
    }
}

// ---------------- kernel 2: weight convert + transpose (validated R8) ----
template<bool W1SEL>
__global__ __launch_bounds__(256) void convert_w(const float* __restrict__ W) {
    __shared__ float tb[64 * 65];
    const int K = W1SEL ? CDIM : HDIM;
    const int N = W1SEL ? HDIM : CDIM;
    __nv_bfloat16* Wt = W1SEL ? g_w1t : g_w2t;
    const float shift = W1SEL ? 0.5f : 0.0f;
    const int e = blockIdx.z;
    const int k0 = blockIdx.x * 64, n0 = blockIdx.y * 64;
    const int tid = threadIdx.x;
    const float* Wp = W + (size_t)e * K * N;

    #pragma unroll
    for (int p = 0; p < 4; ++p) {
        const int idx = tid + p * 256;
        const int row = idx >> 4;
        const int c4  = (idx & 15) * 4;
        const float4 v = *reinterpret_cast<const float4*>(
            &Wp[(size_t)(k0 + row) * N + n0 + c4]);
        float* d = &tb[row * 65 + c4];
        d[0] = v.x; d[1] = v.y; d[2] = v.z; d[3] = v.w;
    }
    __syncthreads();

    __nv_bfloat16* Wo = Wt + (size_t)e * N * K;
    #pragma unroll
    for (int p = 0; p < 2; ++p) {
        const int idx = tid + p * 256;
        const int nrow = idx >> 3;
        const int kseg = (idx & 7) * 8;
        __nv_bfloat162 b[4];
        #pragma unroll
        for (int j = 0; j < 4; ++j)
            b[j] = __floats2bfloat162_rn(tb[(kseg + 2*j    ) * 65 + nrow] - shift,
                                         tb[(kseg + 2*j + 1) * 65 + nrow] - shift);
        *reinterpret_cast<uint4*>(&Wo[(size_t)(n0 + nrow) * K + k0 + kseg]) =
            *reinterpret_cast<const uint4*>(b);
    }
}

// ---- grouped GEMM: BM=BN=128, warp tile 64x32, 2 CTAs/SM, 3 stages ------
// (byte-identical to the R13 passing kernel)
#define TILE0       2048
#define STAGE_BYTES 32768
#define A_BYTES     16384
#define SMEM_TOTAL  (TILE0 + STAGES * STAGE_BYTES)   // 100352 -> 2 CTAs/SM

template<int KDIM, int NDIM, bool FFN1>
__global__ __launch_bounds__(256, 2) void moe_gemm2(
    const float* __restrict__ bias, float* __restrict__ out)
{
    const int e   = blockIdx.z;
    const int cnt = g_cnt[e];
    const int m0  = blockIdx.y * BM;
    if (m0 >= cnt) return;
    const int n0  = blockIdx.x * BN;

    extern __shared__ __align__(1024) char smem[];
    int*   toks = (int*)(smem);            // 128 ints
    float* cs   = (float*)(smem + 512);    // 128 floats
    float* bs   = (float*)(smem + 1024);   // 128 floats
    const uint32_t tiles = smem_u32(smem + TILE0);

    const int tid = threadIdx.x, lane = tid & 31, wid = tid >> 5;

    if (tid < BM) {
        const int tk = g_tok[e * NTOK + min(m0 + tid, cnt - 1)];
        toks[tid] = tk;
        cs[tid]   = FFN1 ? 0.5f * g_xsum[tk] : g_score[tk];
        bs[tid]   = bias[(size_t)e * NDIM + n0 + tid];
    }
    __syncthreads();

    // ---- staging: thread -> (16B chunk, rows rbase+32i), XOR swizzle ----
    const __nv_bfloat16* __restrict__ A  = FFN1 ? g_xb  : g_h;
    const __nv_bfloat16* __restrict__ Wt = (FFN1 ? g_w1t : g_w2t) + (size_t)e * NDIM * KDIM;
    const int chunk = tid & 7;
    const int rbase = tid >> 3;                      // 0..31
    const uint32_t sw    = (uint32_t)((chunk ^ (rbase & 7)) * 16);
    const uint32_t roff0 = (uint32_t)(rbase * 128) + sw;
    const __nv_bfloat16* aptr[4];
    #pragma unroll
    for (int i = 0; i < 4; ++i)
        aptr[i] = A + (size_t)toks[rbase + i * 32] * KDIM + chunk * 8;
    const __nv_bfloat16* bptr0 = Wt + (size_t)(n0 + rbase) * KDIM + chunk * 8;

    auto load_tile = [&](int t, int s) {
        const uint32_t sa = tiles + s * STAGE_BYTES;
        const uint32_t sb = sa + A_BYTES;
        const int ke = t * BK;
        #pragma unroll
        for (int i = 0; i < 4; ++i)
            cpa16(sa + roff0 + i * 4096, aptr[i] + ke);
        #pragma unroll
        for (int i = 0; i < 4; ++i)
            cpa16(sb + roff0 + i * 4096, bptr0 + (size_t)i * 32 * KDIM + ke);
        cpa_commit();
    };

    // ---- warp tiling: 2 (M) x 4 (N) warps, warp tile 64x32 ----
    const int wm = (wid & 1) * 64;
    const int wn = (wid >> 1) * 32;
    const int lane15 = lane & 15;
    const int laneh  = lane >> 4;

    uint32_t arow128[4], arow7[4], brow128[2], brow7[2];
    #pragma unroll
    for (int i = 0; i < 4; ++i) {
        const int ra = wm + i * 16 + lane15;
        arow128[i] = (uint32_t)(ra * 128); arow7[i] = (uint32_t)(ra & 7);
    }
    #pragma unroll
    for (int i = 0; i < 2; ++i) {
        const int rb = wn + i * 16 + lane15;
        brow128[i] = (uint32_t)(rb * 128); brow7[i] = (uint32_t)(rb & 7);
    }

    float c[4][4][4];
    #pragma unroll
    for (int mi = 0; mi < 4; ++mi)
        #pragma unroll
        for (int ni = 0; ni < 4; ++ni)
            #pragma unroll
            for (int q = 0; q < 4; ++q) c[mi][ni][q] = 0.f;

    const int T = KDIM / BK;
    load_tile(0, 0);
    load_tile(1, 1);

    for (int t = 0; t < T; ++t) {
        const int s = t % STAGES;
        cpa_wait1();
        __syncthreads();
        if (t + 2 < T) load_tile(t + 2, (t + 2) % STAGES);
        else cpa_commit();                 // keep group accounting uniform

        const uint32_t Ab = tiles + s * STAGE_BYTES;
        const uint32_t Bb = Ab + A_BYTES;
        #pragma unroll
        for (int ki = 0; ki < 4; ++ki) {
            const uint32_t ck = (uint32_t)(ki * 2 + laneh);
            uint32_t a[4][4], b[2][4];
            #pragma unroll
            for (int i = 0; i < 4; ++i)
                ldsm_x4(a[i], Ab + arow128[i] + ((ck ^ arow7[i]) << 4));
            #pragma unroll
            for (int i = 0; i < 2; ++i)
                ldsm_x4(b[i], Bb + brow128[i] + ((ck ^ brow7[i]) << 4));
            #pragma unroll
            for (int mi = 0; mi < 4; ++mi)
                #pragma unroll
                for (int n8 = 0; n8 < 4; ++n8) {
                    const int ni = n8 >> 1, o = n8 & 1;
                    mma_bf16(c[mi][n8], a[mi], b[ni][o], b[ni][o + 2]);
                }
        }
    }

    // ---------------- epilogue ----------------
    const int g  = lane >> 2;
    const int t4 = lane & 3;
    #pragma unroll
    for (int mi = 0; mi < 4; ++mi) {
        #pragma unroll
        for (int h = 0; h < 2; ++h) {
            const int r = wm + mi * 16 + g + h * 8;
            if (m0 + r < cnt) {
                const int   tok  = toks[r];
                const float corr = cs[r];
                #pragma unroll
                for (int n8 = 0; n8 < 4; ++n8) {
                    const int col = wn + n8 * 8 + t4 * 2;
                    const float v0 = c[mi][n8][h * 2 + 0] + bs[col];
                    const float v1 = c[mi][n8][h * 2 + 1] + bs[col + 1];
                    if (FFN1) {
                        *reinterpret_cast<__nv_bfloat162*>(
                            &g_h[(size_t)tok * HDIM + n0 + col]) =
                            __floats2bfloat162_rn(gelu_exact(v0 + corr),
                                                  gelu_exact(v1 + corr));
                    } else {
                        float2 o2;
                        o2.x = v0 * corr;
                        o2.y = v1 * corr;
                        *reinterpret_cast<float2*>(
                            &out[(size_t)tok * CDIM + n0 + col]) = o2;
                    }
                }
            }
        }
    }
}

// ---------------- launch: fork/join stream topology (validated R12/R13) --
extern "C" void kernel_launch(void* const* d_in, const int* in_sizes, int n_in,
                              void* d_out, int out_size) {
    (void)in_sizes; (void)n_in; (void)out_size;
    const float* x  = (const float*)d_in[0];
    const float* Wr = (const float*)d_in[1];
    const float* wg = (const float*)d_in[2];
    const float* W1 = (const float*)d_in[3];
    const float* b1 = (const float*)d_in[4];
    const float* W2 = (const float*)d_in[5];
    const float* b2 = (const float*)d_in[6];
    float* out = (float*)d_out;

    cudaFuncSetAttribute(moe_gemm2<CDIM, HDIM, true>,
                         cudaFuncAttributeMaxDynamicSharedMemorySize, SMEM_TOTAL);
    cudaFuncSetAttribute(moe_gemm2<HDIM, CDIM, false>,
                         cudaFuncAttributeMaxDynamicSharedMemorySize, SMEM_TOTAL);

    cudaStream_t s2;
    cudaStreamCreateWithFlags(&s2, cudaStreamNonBlocking);
    cudaEvent_t evZero, evRoute, evConv2;
    cudaEventCreateWithFlags(&evZero,  cudaEventDisableTiming);
    cudaEventCreateWithFlags(&evRoute, cudaEventDisableTiming);
    cudaEventCreateWithFlags(&evConv2, cudaEventDisableTiming);

    zero_cnt_kernel<<<1, 32>>>();
    cudaEventRecord(evZero, 0);

    cudaStreamWaitEvent(s2, evZero, 0);
    route_kernel<<<NTOK / (2 * 8), 256, 0, s2>>>(x, Wr, wg);
    cudaEventRecord(evRoute, s2);
    convert_w<false><<<dim3(HDIM / 64, CDIM / 64, NEXP), 256, 0, s2>>>(W2);
    cudaEventRecord(evConv2, s2);

    convert_w<true ><<<dim3(CDIM / 64, HDIM / 64, NEXP), 256>>>(W1);
    cudaStreamWaitEvent(0, evRoute, 0);
    moe_gemm2<CDIM, HDIM, true ><<<dim3(HDIM / BN, NTOK / BM, NEXP), 256, SMEM_TOTAL>>>(b1, nullptr);
    cudaStreamWaitEvent(0, evConv2, 0);
    moe_gemm2<HDIM, CDIM, false><<<dim3(CDIM / BN, NTOK / BM, NEXP), 256, SMEM_TOTAL>>>(b2, out);

    cudaEventDestroy(evZero);
    cudaEventDestroy(evRoute);
    cudaEventDestroy(evConv2);
    cudaStreamDestroy(s2);
}